// round 4
// baseline (speedup 1.0000x reference)
#include <cuda_runtime.h>
#include <math.h>

#define NGRAPH 64
#define LNODES 2048
#define DDIM   128
#define SPLITK 4
#define CHUNK  (LNODES / SPLITK)   // 512
#define PAD    132

// Scratch (no allocations allowed): Gram partials + transposed squared weights.
__device__ float g_gram_part[NGRAPH * SPLITK * DDIM * DDIM];  // 16 MB
__device__ float g_w2t[DDIM * DDIM];                          // w2t[d*128+p] = w[p][d]^2

// ---------------------------------------------------------------------------
// Kernel 0: w2t[d][p] = w[p][d]^2
// ---------------------------------------------------------------------------
__global__ void k_w2t(const float* __restrict__ w) {
    int idx = blockIdx.x * 256 + threadIdx.x;   // 0..16383
    int d = idx >> 7, p = idx & 127;
    float v = w[p * DDIM + d];
    g_w2t[idx] = v * v;                          // idx == d*128 + p
}

// ---------------------------------------------------------------------------
// Kernel 1: Gram partials. block b: graph j = b>>2, chunk c = b&3 (512 rows).
// Gram_part[b] = X_chunk^T X_chunk  (128x128)
// ---------------------------------------------------------------------------
__global__ void __launch_bounds__(256) k_gram(const float* __restrict__ feats) {
    __shared__ float xs[32 * DDIM];             // 16 KB row-chunk
    int b  = blockIdx.x;
    int gj = b >> 2, ck = b & 3;
    const float4* X4 = (const float4*)(feats + ((size_t)gj * LNODES + (size_t)ck * CHUNK) * DDIM);

    int tid = threadIdx.x;
    int ty = tid >> 4, tx = tid & 15;

    float acc[8][8];
#pragma unroll
    for (int i = 0; i < 8; i++)
#pragma unroll
        for (int j = 0; j < 8; j++) acc[i][j] = 0.f;

    float4* xs4 = (float4*)xs;
    for (int k0 = 0; k0 < CHUNK; k0 += 32) {
        __syncthreads();
#pragma unroll
        for (int t = 0; t < 4; t++)
            xs4[tid + t * 256] = X4[(size_t)k0 * 32 + tid + t * 256];
        __syncthreads();
#pragma unroll 8
        for (int k = 0; k < 32; k++) {
            float4 a0 = *(const float4*)&xs[k * DDIM + ty * 8];
            float4 a1 = *(const float4*)&xs[k * DDIM + ty * 8 + 4];
            float4 b0 = *(const float4*)&xs[k * DDIM + tx * 8];
            float4 b1 = *(const float4*)&xs[k * DDIM + tx * 8 + 4];
            float av[8] = {a0.x,a0.y,a0.z,a0.w,a1.x,a1.y,a1.z,a1.w};
            float bv[8] = {b0.x,b0.y,b0.z,b0.w,b1.x,b1.y,b1.z,b1.w};
#pragma unroll
            for (int i = 0; i < 8; i++)
#pragma unroll
                for (int j = 0; j < 8; j++)
                    acc[i][j] = fmaf(av[i], bv[j], acc[i][j]);
        }
    }
    float* outp = g_gram_part + (size_t)b * DDIM * DDIM;
#pragma unroll
    for (int i = 0; i < 8; i++) {
        *(float4*)&outp[(ty * 8 + i) * DDIM + tx * 8]     = make_float4(acc[i][0], acc[i][1], acc[i][2], acc[i][3]);
        *(float4*)&outp[(ty * 8 + i) * DDIM + tx * 8 + 4] = make_float4(acc[i][4], acc[i][5], acc[i][6], acc[i][7]);
    }
}

// ---------------------------------------------------------------------------
// Kernel 2: fused main. block = 128 rows of one graph.
//   v2 = v1 @ Gram[partner]   (pass1, computed transposed via Gram symmetry)
//   out = (v1*v2)@W2T / max(sqrt((v1^2@W2T)*(v2^2@W2T)), eps)   (pass2, fused)
// ---------------------------------------------------------------------------
__global__ void __launch_bounds__(256) k_main(const float* __restrict__ feats,
                                              float* __restrict__ out) {
    extern __shared__ float sm[];
    float* mat = sm;                     // 128 x PAD : Gram then W2T
    float* v1t = sm + DDIM * PAD;        // 128 x PAD : V1^T  ([d][l])
    float* v2t = sm + 2 * DDIM * PAD;    // 128 x PAD : V2^T  ([d][l])

    int b    = blockIdx.x;               // 0..1023
    int gj   = b >> 4;                   // graph 0..63
    int tile = b & 15;
    int row0 = gj * LNODES + tile * 128;
    int tid  = threadIdx.x;

    // ---- load V1 tile transposed into smem ----
    const float4* F4 = (const float4*)(feats + (size_t)row0 * DDIM);
#pragma unroll
    for (int t = 0; t < 16; t++) {
        int f  = tid + t * 256;          // 0..4095 float4s
        int l  = f >> 5;                 // local row 0..127
        int d4 = f & 31;
        float4 v = F4[f];
        v1t[(d4 * 4 + 0) * PAD + l] = v.x;
        v1t[(d4 * 4 + 1) * PAD + l] = v.y;
        v1t[(d4 * 4 + 2) * PAD + l] = v.z;
        v1t[(d4 * 4 + 3) * PAD + l] = v.w;
    }
    // ---- load partner Gram (sum of 4 split-K partials) ----
    {
        int partner = gj ^ 1;
        const float* gp = g_gram_part + (size_t)partner * SPLITK * DDIM * DDIM;
        for (int e = tid; e < DDIM * DDIM; e += 256) {
            float s = gp[e] + gp[e + DDIM * DDIM] + gp[e + 2 * DDIM * DDIM] + gp[e + 3 * DDIM * DDIM];
            mat[(e >> 7) * PAD + (e & 127)] = s;
        }
    }
    __syncthreads();

    int ty = tid >> 4, tx = tid & 15;

    // ---- pass1: V2^T[dout][l] = sum_din Gram[din][dout] * V1^T[din][l] ----
    {
        float acc[8][8];
#pragma unroll
        for (int i = 0; i < 8; i++)
#pragma unroll
            for (int j = 0; j < 8; j++) acc[i][j] = 0.f;

#pragma unroll 4
        for (int d = 0; d < DDIM; d++) {
            float4 a0 = *(const float4*)&mat[d * PAD + ty * 8];
            float4 a1 = *(const float4*)&mat[d * PAD + ty * 8 + 4];
            float4 b0 = *(const float4*)&v1t[d * PAD + tx * 8];
            float4 b1 = *(const float4*)&v1t[d * PAD + tx * 8 + 4];
            float av[8] = {a0.x,a0.y,a0.z,a0.w,a1.x,a1.y,a1.z,a1.w};
            float bv[8] = {b0.x,b0.y,b0.z,b0.w,b1.x,b1.y,b1.z,b1.w};
#pragma unroll
            for (int i = 0; i < 8; i++)
#pragma unroll
                for (int j = 0; j < 8; j++)
                    acc[i][j] = fmaf(av[i], bv[j], acc[i][j]);
        }
        __syncthreads();   // everyone done reading mat (Gram) and v1t for pass1
#pragma unroll
        for (int i = 0; i < 8; i++) {
            *(float4*)&v2t[(ty * 8 + i) * PAD + tx * 8]     = make_float4(acc[i][0], acc[i][1], acc[i][2], acc[i][3]);
            *(float4*)&v2t[(ty * 8 + i) * PAD + tx * 8 + 4] = make_float4(acc[i][4], acc[i][5], acc[i][6], acc[i][7]);
        }
    }
    // ---- overwrite mat with W2T ----
    for (int e = tid; e < DDIM * DDIM; e += 256)
        mat[(e >> 7) * PAD + (e & 127)] = g_w2t[e];
    __syncthreads();

    // ---- pass2: fused triple GEMM (num, n1sq, n2sq) ----
    float aN[8][8], a1s[8][8], a2s[8][8];
#pragma unroll
    for (int i = 0; i < 8; i++)
#pragma unroll
        for (int j = 0; j < 8; j++) { aN[i][j] = 0.f; a1s[i][j] = 0.f; a2s[i][j] = 0.f; }

#pragma unroll 2
    for (int d = 0; d < DDIM; d++) {
        float4 x0 = *(const float4*)&v1t[d * PAD + ty * 8];
        float4 x1 = *(const float4*)&v1t[d * PAD + ty * 8 + 4];
        float4 y0 = *(const float4*)&v2t[d * PAD + ty * 8];
        float4 y1 = *(const float4*)&v2t[d * PAD + ty * 8 + 4];
        float4 b0 = *(const float4*)&mat[d * PAD + tx * 8];
        float4 b1 = *(const float4*)&mat[d * PAD + tx * 8 + 4];
        float xv[8] = {x0.x,x0.y,x0.z,x0.w,x1.x,x1.y,x1.z,x1.w};
        float yv[8] = {y0.x,y0.y,y0.z,y0.w,y1.x,y1.y,y1.z,y1.w};
        float bv[8] = {b0.x,b0.y,b0.z,b0.w,b1.x,b1.y,b1.z,b1.w};
#pragma unroll
        for (int i = 0; i < 8; i++) {
            float pn = xv[i] * yv[i];
            float p1 = xv[i] * xv[i];
            float p2 = yv[i] * yv[i];
#pragma unroll
            for (int j = 0; j < 8; j++) {
                aN[i][j]  = fmaf(pn, bv[j], aN[i][j]);
                a1s[i][j] = fmaf(p1, bv[j], a1s[i][j]);
                a2s[i][j] = fmaf(p2, bv[j], a2s[i][j]);
            }
        }
    }

    // ---- epilogue: out = num / max(sqrt(n1sq*n2sq), eps) ----
#pragma unroll
    for (int i = 0; i < 8; i++) {
        int row = row0 + ty * 8 + i;
        float r[8];
#pragma unroll
        for (int j = 0; j < 8; j++) {
            float den = sqrtf(a1s[i][j] * a2s[i][j]);
            den = fmaxf(den, 1e-8f);
            r[j] = aN[i][j] / den;
        }
        *(float4*)&out[(size_t)row * DDIM + tx * 8]     = make_float4(r[0], r[1], r[2], r[3]);
        *(float4*)&out[(size_t)row * DDIM + tx * 8 + 4] = make_float4(r[4], r[5], r[6], r[7]);
    }
}

// ---------------------------------------------------------------------------
extern "C" void kernel_launch(void* const* d_in, const int* in_sizes, int n_in,
                              void* d_out, int out_size) {
    // Identify inputs robustly by element count:
    //   feats: 131072*128 = 16777216, mp_w: 128*128 = 16384
    const float* feats = nullptr;
    const float* mp_w  = nullptr;
    for (int i = 0; i < n_in; i++) {
        if (in_sizes[i] == 16777216)     feats = (const float*)d_in[i];
        else if (in_sizes[i] == 16384)   mp_w  = (const float*)d_in[i];
    }
    float* out = (float*)d_out;
    if (!feats || !mp_w || !out) return;

    const int smem_bytes = 3 * DDIM * PAD * (int)sizeof(float);   // 202752
    cudaFuncSetAttribute((const void*)k_main,
                         cudaFuncAttributeMaxDynamicSharedMemorySize, smem_bytes);

    k_w2t <<<64, 256>>>(mp_w);
    k_gram<<<NGRAPH * SPLITK, 256>>>(feats);
    k_main<<<NGRAPH * (LNODES / 128), 256, smem_bytes>>>(feats, out);
}